// round 6
// baseline (speedup 1.0000x reference)
#include <cuda_runtime.h>
#include <math.h>

#define RR 16
#define GG 4096
#define KN 8
#define HID 64
#define BATCH 4
#define NPTS 4096
#define CHUNK 2048

// ---------------- device scratch (no allocations allowed) ----------------
__device__ int   g_knn[BATCH * GG * KN];
__device__ float g_vol[BATCH * HID * GG];     // vol after edge net, [b][c][16^3]
__device__ float g_t1[BATCH * HID * GG];      // conv intermediates
__device__ float g_t2[BATCH * HID * GG];
__device__ float g_vol2[BATCH * HID * 512];   // after maxpool, [b][c][8^3]
__device__ float g_mean[HID];
__device__ float g_inv[HID];
__device__ float g_sum_bc[BATCH * HID];
__device__ float g_ssq_bc[BATCH * HID];

__device__ __forceinline__ float gelu_f(float v) {
    // jax.nn.gelu approximate=True (tanh form)
    const float c = 0.7978845608028654f;
    float t = tanhf(c * (v + 0.044715f * v * v * v));
    return 0.5f * v * (1.0f + t);
}

// linspace(-1,1,16) bit-exact: rn(-1 + rn(i * rn(2/15)))
__device__ __forceinline__ float grid_coord(int i) {
    const float delta = 2.0f / 15.0f;   // compile-time correctly-rounded fp32
    return __fadd_rn(-1.0f, __fmul_rn((float)i, delta));
}

// ---------------- KNN: warp per (b, g) voxel ----------------
// Distances computed bit-matching the reference:
//   gn = (gx*gx + gy*gy) + gz*gz          (mul/add, no fma — XLA reduce)
//   pn likewise
//   e  = fma(gz,pz, fma(gy,py, fma(gx,px, 0)))   (cublas SGEMM k-ascending FFMA chain)
//   d  = (gn + pn) - 2*e
// Tie-break on equal d by smaller point index (stable top_k).
__global__ void knn_kernel(const float* __restrict__ pos) {
    __shared__ float px[CHUNK], py[CHUNK], pz[CHUNK], pn[CHUNK];
    int b = blockIdx.y;
    int t = threadIdx.x;
    int warp = t >> 5, lane = t & 31;
    int g = blockIdx.x * 8 + warp;

    float gx = grid_coord(g >> 8);
    float gy = grid_coord((g >> 4) & 15);
    float gz = grid_coord(g & 15);
    float gn = __fadd_rn(__fadd_rn(__fmul_rn(gx, gx), __fmul_rn(gy, gy)), __fmul_rn(gz, gz));

    float bd[KN]; int bi[KN];
#pragma unroll
    for (int j = 0; j < KN; j++) { bd[j] = 3e38f; bi[j] = 0x7fffffff; }
    float worst = 3e38f; int ws = 0;

    for (int base = 0; base < NPTS; base += CHUNK) {
        __syncthreads();
        const float* pb = pos + (b * NPTS + base) * 3;
        for (int i = t; i < CHUNK; i += 256) {
            float x = pb[i * 3 + 0], y = pb[i * 3 + 1], z = pb[i * 3 + 2];
            px[i] = x; py[i] = y; pz[i] = z;
            pn[i] = __fadd_rn(__fadd_rn(__fmul_rn(x, x), __fmul_rn(y, y)), __fmul_rn(z, z));
        }
        __syncthreads();

        for (int n = lane; n < CHUNK; n += 32) {
            float e = fmaf(gz, pz[n], fmaf(gy, py[n], fmaf(gx, px[n], 0.0f)));
            float d = __fsub_rn(__fadd_rn(gn, pn[n]), __fmul_rn(2.0f, e));
            if (d < worst) {
                // new point index is larger than all stored; strict < is the
                // correct lexicographic (d, n) acceptance.
                int nidx = base + n;
#pragma unroll
                for (int j = 0; j < KN; j++) if (j == ws) { bd[j] = d; bi[j] = nidx; }
                // recompute lexicographic max (evict largest (d, n))
                worst = bd[0]; int wi = bi[0]; ws = 0;
#pragma unroll
                for (int j = 1; j < KN; j++)
                    if (bd[j] > worst || (bd[j] == worst && bi[j] > wi)) {
                        worst = bd[j]; wi = bi[j]; ws = j;
                    }
            }
        }
    }

    // merge 32 lanes x 8 -> global top-8, ascending (d, index) extraction
    unsigned used = 0;
    for (int sel = 0; sel < KN; sel++) {
        float lv = 3e38f; int li = 0x7fffffff; int ls = -1;
#pragma unroll
        for (int j = 0; j < KN; j++)
            if (!((used >> j) & 1u) && (bd[j] < lv || (bd[j] == lv && bi[j] < li))) {
                lv = bd[j]; li = bi[j]; ls = j;
            }
        float v = lv; int vi = li; int vl = lane;
#pragma unroll
        for (int off = 16; off; off >>= 1) {
            float ov = __shfl_xor_sync(0xffffffffu, v, off);
            int   oi = __shfl_xor_sync(0xffffffffu, vi, off);
            int   ol = __shfl_xor_sync(0xffffffffu, vl, off);
            if (ov < v || (ov == v && oi < vi)) { v = ov; vi = oi; vl = ol; }
        }
        if (lane == 0) g_knn[(b * GG + g) * KN + sel] = vi;
        if (lane == vl) {
#pragma unroll
            for (int j = 0; j < KN; j++) if (j == ls) used |= (1u << j);
        }
    }
}

// ---------------- Edge (BipartiteConv + update net): warp per voxel ----------------
__global__ void edge_kernel(const float* __restrict__ pos, const float* __restrict__ xin,
                            const float* __restrict__ pe_w1, const float* __restrict__ pe_b1,
                            const float* __restrict__ pe_w2, const float* __restrict__ pe_b2,
                            const float* __restrict__ f_w, const float* __restrict__ f_b,
                            const float* __restrict__ up_w, const float* __restrict__ up_b) {
    __shared__ __align__(16) float s_w2[HID * HID];
    __shared__ float s_pw1[3 * HID], s_pb1[HID], s_pb2[HID], s_fw[3 * HID], s_fb[HID];
    __shared__ __align__(16) float s_h1[8][KN][HID];
    __shared__ __align__(16) float s_agg[8][HID];

    int t = threadIdx.x;
    for (int i = t; i < HID * HID; i += 256) s_w2[i] = pe_w2[i];
    if (t < 192) { s_pw1[t] = pe_w1[t]; s_fw[t] = f_w[t]; }
    if (t < 64)  { s_pb1[t] = pe_b1[t]; s_pb2[t] = pe_b2[t]; s_fb[t] = f_b[t]; }
    __syncthreads();

    int warp = t >> 5, lane = t & 31;
    int b = blockIdx.y;
    int g = blockIdx.x * 8 + warp;
    float gx = grid_coord(g >> 8);
    float gy = grid_coord((g >> 4) & 15);
    float gz = grid_coord(g & 15);

    int o0 = 2 * lane, o1 = o0 + 1;
    float fm0[KN], fm1[KN];

#pragma unroll
    for (int k = 0; k < KN; k++) {
        int nidx = g_knn[(b * GG + g) * KN + k];
        const float* pp = pos + (b * NPTS + nidx) * 3;
        float rx = pp[0] - gx, ry = pp[1] - gy, rz = pp[2] - gz;
        const float* xp = xin + (b * NPTS + nidx) * 3;
        float f0 = xp[0], f1 = xp[1], f2 = xp[2];

        float h0 = s_pb1[o0] + rx * s_pw1[o0] + ry * s_pw1[64 + o0] + rz * s_pw1[128 + o0];
        float h1 = s_pb1[o1] + rx * s_pw1[o1] + ry * s_pw1[64 + o1] + rz * s_pw1[128 + o1];
        s_h1[warp][k][o0] = gelu_f(h0);
        s_h1[warp][k][o1] = gelu_f(h1);

        fm0[k] = s_fb[o0] + f0 * s_fw[o0] + f1 * s_fw[64 + o0] + f2 * s_fw[128 + o0];
        fm1[k] = s_fb[o1] + f0 * s_fw[o1] + f1 * s_fw[64 + o1] + f2 * s_fw[128 + o1];
    }
    __syncwarp();

    float a0 = 0.0f, a1 = 0.0f;
    for (int k = 0; k < KN; k++) {
        float pe0 = s_pb2[o0], pe1 = s_pb2[o1];
#pragma unroll
        for (int c = 0; c < HID; c += 4) {
            float4 av = *(const float4*)&s_h1[warp][k][c];
            float2 w0 = *(const float2*)&s_w2[(c + 0) * HID + o0];
            float2 w1 = *(const float2*)&s_w2[(c + 1) * HID + o0];
            float2 w2 = *(const float2*)&s_w2[(c + 2) * HID + o0];
            float2 w3 = *(const float2*)&s_w2[(c + 3) * HID + o0];
            pe0 = fmaf(av.x, w0.x, fmaf(av.y, w1.x, fmaf(av.z, w2.x, fmaf(av.w, w3.x, pe0))));
            pe1 = fmaf(av.x, w0.y, fmaf(av.y, w1.y, fmaf(av.z, w2.y, fmaf(av.w, w3.y, pe1))));
        }
        a0 = fmaf(pe0, fm0[k], a0);
        a1 = fmaf(pe1, fm1[k], a1);
    }
    a0 *= (1.0f / KN);
    a1 *= (1.0f / KN);
    s_agg[warp][o0] = a0;
    s_agg[warp][o1] = a1;
    __syncwarp();

    float u0 = up_b[o0], u1 = up_b[o1];
#pragma unroll
    for (int c = 0; c < HID; c += 4) {
        float4 av = *(const float4*)&s_agg[warp][c];
        float2 w0 = *(const float2*)&up_w[(c + 0) * HID + o0];
        float2 w1 = *(const float2*)&up_w[(c + 1) * HID + o0];
        float2 w2 = *(const float2*)&up_w[(c + 2) * HID + o0];
        float2 w3 = *(const float2*)&up_w[(c + 3) * HID + o0];
        u0 = fmaf(av.x, w0.x, fmaf(av.y, w1.x, fmaf(av.z, w2.x, fmaf(av.w, w3.x, u0))));
        u1 = fmaf(av.x, w0.y, fmaf(av.y, w1.y, fmaf(av.z, w2.y, fmaf(av.w, w3.y, u1))));
    }
    u0 = gelu_f(u0);
    u1 = gelu_f(u1);

    // vol[b][c][iz][iy][ix], g = ix*256 + iy*16 + iz
    int iz = g & 15, iy = (g >> 4) & 15, ix = g >> 8;
    int sp = iz * 256 + iy * 16 + ix;
    g_vol[(b * HID + o0) * GG + sp] = u0;
    g_vol[(b * HID + o1) * GG + sp] = u1;
}

// ---------------- direct 3x3x3 conv, SAME, 64->64 ----------------
template <int DIM, int CI, int OG, bool BNRELU>
__global__ void conv_kernel(const float* __restrict__ in, const float* __restrict__ w,
                            const float* __restrict__ bias, float* __restrict__ out) {
    constexpr int P = DIM + 2;
    __shared__ float s_in[3 * CI * P * P];
    __shared__ __align__(16) float s_w[27 * CI * OG];

    int z = blockIdx.x, b = blockIdx.y, o0 = blockIdx.z * OG;
    int t = threadIdx.x;
    int y = t / DIM, x = t % DIM;

    float acc[OG];
#pragma unroll
    for (int q = 0; q < OG; q++) acc[q] = bias[o0 + q];

    for (int cc = 0; cc < HID; cc += CI) {
        __syncthreads();
        for (int i = t; i < 3 * CI * P * P; i += DIM * DIM) {
            int xx = i % P; int r = i / P; int yy = r % P; r /= P;
            int ci = r % CI; int pz = r / CI;
            int gz = z + pz - 1, gy = yy - 1, gx = xx - 1;
            float v = 0.0f;
            if (gz >= 0 && gz < DIM && gy >= 0 && gy < DIM && gx >= 0 && gx < DIM) {
                v = in[(((b * HID + cc + ci) * DIM + gz) * DIM + gy) * DIM + gx];
                if (BNRELU) v = fmaxf(0.0f, (v - g_mean[cc + ci]) * g_inv[cc + ci]);
            }
            s_in[i] = v;
        }
        for (int i = t; i < 27 * CI * OG; i += DIM * DIM) {
            int og = i % OG; int r = i / OG; int ci = r % CI; int tap = r / CI;
            s_w[i] = w[((o0 + og) * HID + cc + ci) * 27 + tap];
        }
        __syncthreads();

#pragma unroll 1
        for (int tap = 0; tap < 27; tap++) {
            int kd = tap / 9, kh = (tap / 3) % 3, kw = tap % 3;
            const float* ap = &s_in[(kd * CI) * P * P + (y + kh) * P + (x + kw)];
            const float4* wp = (const float4*)&s_w[tap * CI * OG];
#pragma unroll
            for (int ci = 0; ci < CI; ci++) {
                float a = ap[ci * P * P];
#pragma unroll
                for (int q = 0; q < OG / 4; q++) {
                    float4 wv = wp[ci * (OG / 4) + q];
                    acc[4 * q + 0] = fmaf(a, wv.x, acc[4 * q + 0]);
                    acc[4 * q + 1] = fmaf(a, wv.y, acc[4 * q + 1]);
                    acc[4 * q + 2] = fmaf(a, wv.z, acc[4 * q + 2]);
                    acc[4 * q + 3] = fmaf(a, wv.w, acc[4 * q + 3]);
                }
            }
        }
    }
    int spatial = DIM * DIM * DIM;
#pragma unroll
    for (int q = 0; q < OG; q++)
        out[(b * HID + o0 + q) * spatial + (z * DIM + y) * DIM + x] = acc[q];
}

// ---------------- per-channel BN stats ----------------
__global__ void stats_kernel(const float* __restrict__ buf, int spatial) {
    int c = blockIdx.x, t = threadIdx.x;
    float s = 0.0f, q = 0.0f;
    for (int b = 0; b < BATCH; b++) {
        const float* p = buf + (b * HID + c) * spatial;
        for (int r = t; r < spatial; r += 256) {
            float v = p[r];
            s += v; q += v * v;
        }
    }
#pragma unroll
    for (int off = 16; off; off >>= 1) {
        s += __shfl_xor_sync(0xffffffffu, s, off);
        q += __shfl_xor_sync(0xffffffffu, q, off);
    }
    __shared__ float ss[8], sq[8];
    int warp = t >> 5, lane = t & 31;
    if (lane == 0) { ss[warp] = s; sq[warp] = q; }
    __syncthreads();
    if (t == 0) {
        float S = 0.0f, Q = 0.0f;
        for (int j = 0; j < 8; j++) { S += ss[j]; Q += sq[j]; }
        float n = (float)(BATCH * spatial);
        float m = S / n;
        float var = Q / n - m * m;
        g_mean[c] = m;
        g_inv[c] = rsqrtf(var + 1e-5f);
    }
}

// ---------------- block0: residual + relu + 2x2x2 maxpool ----------------
__global__ void resid_pool_kernel(const float* __restrict__ vol, const float* __restrict__ t2) {
    int c = blockIdx.x, b = blockIdx.y, t = threadIdx.x;  // 512 threads
    float m = g_mean[c], iv = g_inv[c];
    int z = t >> 6, y = (t >> 3) & 7, x = t & 7;
    const float* vb = vol + (b * HID + c) * 4096;
    const float* tb = t2 + (b * HID + c) * 4096;
    float best = 0.0f;  // relu outputs are >= 0
#pragma unroll
    for (int dz = 0; dz < 2; dz++)
#pragma unroll
        for (int dy = 0; dy < 2; dy++)
#pragma unroll
            for (int dx = 0; dx < 2; dx++) {
                int idx = ((2 * z + dz) * 16 + 2 * y + dy) * 16 + 2 * x + dx;
                float v = fmaxf(0.0f, vb[idx] + (tb[idx] - m) * iv);
                best = fmaxf(best, v);
            }
    g_vol2[(b * HID + c) * 512 + t] = best;
}

// ---------------- block1: residual + relu, reduce to per-(b,c) sums ----------------
__global__ void resid_sum_kernel(const float* __restrict__ vol2, const float* __restrict__ t2) {
    int c = blockIdx.x, b = blockIdx.y, t = threadIdx.x;  // 512 threads
    float m = g_mean[c], iv = g_inv[c];
    float v = fmaxf(0.0f, vol2[(b * HID + c) * 512 + t] + (t2[(b * HID + c) * 512 + t] - m) * iv);
    float s = v, q = v * v;
#pragma unroll
    for (int off = 16; off; off >>= 1) {
        s += __shfl_xor_sync(0xffffffffu, s, off);
        q += __shfl_xor_sync(0xffffffffu, q, off);
    }
    __shared__ float ss[16], sq[16];
    int warp = t >> 5, lane = t & 31;
    if (lane == 0) { ss[warp] = s; sq[warp] = q; }
    __syncthreads();
    if (t == 0) {
        float S = 0.0f, Q = 0.0f;
        for (int j = 0; j < 16; j++) { S += ss[j]; Q += sq[j]; }
        g_sum_bc[b * HID + c] = S;
        g_ssq_bc[b * HID + c] = Q;
    }
}

// ---------------- final BN + affine + spatial mean + linear head ----------------
__global__ void head_kernel(const float* __restrict__ on_g, const float* __restrict__ on_b,
                            const float* __restrict__ ro_w, const float* __restrict__ ro_b,
                            float* __restrict__ out) {
    __shared__ float pooled[BATCH][HID];
    int t = threadIdx.x;  // 64 threads
    if (t < HID) {
        float S = 0.0f, Q = 0.0f;
        for (int b = 0; b < BATCH; b++) { S += g_sum_bc[b * HID + t]; Q += g_ssq_bc[b * HID + t]; }
        float n = (float)(BATCH * 512);
        float m = S / n;
        float var = Q / n - m * m;
        float iv = rsqrtf(var + 1e-5f);
        for (int b = 0; b < BATCH; b++)
            pooled[b][t] = (g_sum_bc[b * HID + t] * (1.0f / 512.0f) - m) * iv * on_g[t] + on_b[t];
    }
    __syncthreads();
    if (t < 64) {
        int b = t >> 4, j = t & 15;
        float s = ro_b[j];
        for (int c = 0; c < HID; c++) s = fmaf(pooled[b][c], ro_w[c * 16 + j], s);
        out[b * 16 + j] = s;
    }
}

// ---------------- launch ----------------
extern "C" void kernel_launch(void* const* d_in, const int* in_sizes, int n_in,
                              void* d_out, int out_size) {
    const float* pos   = (const float*)d_in[0];
    const float* xin   = (const float*)d_in[1];
    const float* pe_w1 = (const float*)d_in[2];
    const float* pe_b1 = (const float*)d_in[3];
    const float* pe_w2 = (const float*)d_in[4];
    const float* pe_b2 = (const float*)d_in[5];
    const float* f_w   = (const float*)d_in[6];
    const float* f_b   = (const float*)d_in[7];
    const float* up_w  = (const float*)d_in[8];
    const float* up_b  = (const float*)d_in[9];
    const float* conv_w = (const float*)d_in[10];  // [2,2,64,64,3,3,3]
    const float* conv_b = (const float*)d_in[11];  // [2,2,64]
    const float* on_g  = (const float*)d_in[12];
    const float* on_b  = (const float*)d_in[13];
    const float* ro_w  = (const float*)d_in[14];
    const float* ro_b  = (const float*)d_in[15];
    float* out = (float*)d_out;

    float *t1, *t2, *vol, *vol2;
    cudaGetSymbolAddress((void**)&t1, g_t1);
    cudaGetSymbolAddress((void**)&t2, g_t2);
    cudaGetSymbolAddress((void**)&vol, g_vol);
    cudaGetSymbolAddress((void**)&vol2, g_vol2);

    const int WSTRIDE = HID * HID * 27;

    knn_kernel<<<dim3(512, BATCH), 256>>>(pos);
    edge_kernel<<<dim3(512, BATCH), 256>>>(pos, xin, pe_w1, pe_b1, pe_w2, pe_b2,
                                           f_w, f_b, up_w, up_b);

    // block 0 @ 16^3
    conv_kernel<16, 4, 32, false><<<dim3(16, BATCH, 2), 256>>>(vol, conv_w + 0 * WSTRIDE,
                                                               conv_b + 0 * HID, t1);
    stats_kernel<<<64, 256>>>(t1, 4096);
    conv_kernel<16, 4, 32, true><<<dim3(16, BATCH, 2), 256>>>(t1, conv_w + 1 * WSTRIDE,
                                                              conv_b + 1 * HID, t2);
    stats_kernel<<<64, 256>>>(t2, 4096);
    resid_pool_kernel<<<dim3(64, BATCH), 512>>>(vol, t2);

    // block 1 @ 8^3
    conv_kernel<8, 16, 8, false><<<dim3(8, BATCH, 8), 64>>>(vol2, conv_w + 2 * WSTRIDE,
                                                            conv_b + 2 * HID, t1);
    stats_kernel<<<64, 256>>>(t1, 512);
    conv_kernel<8, 16, 8, true><<<dim3(8, BATCH, 8), 64>>>(t1, conv_w + 3 * WSTRIDE,
                                                           conv_b + 3 * HID, t2);
    stats_kernel<<<64, 256>>>(t2, 512);
    resid_sum_kernel<<<dim3(64, BATCH), 512>>>(vol2, t2);

    head_kernel<<<1, 64>>>(on_g, on_b, ro_w, ro_b, out);
}

// round 8
// speedup vs baseline: 1.1561x; 1.1561x over previous
#include <cuda_runtime.h>
#include <math.h>

#define RR 16
#define GG 4096
#define KN 8
#define HID 64
#define BATCH 4
#define NPTS 4096
#define CHUNK 2048

typedef unsigned long long u64;

// ---------------- device scratch (no allocations allowed) ----------------
__device__ int   g_knn[BATCH * GG * KN];
__device__ float g_vol[BATCH * HID * GG];     // vol after edge net, [b][c][16^3]
__device__ float g_t1[BATCH * HID * GG];      // conv intermediates
__device__ float g_t2[BATCH * HID * GG];
__device__ float g_vol2[BATCH * HID * 512];   // after maxpool, [b][c][8^3]
__device__ float g_mean[HID];
__device__ float g_inv[HID];
__device__ float g_ps[64 * HID];              // per-block partial sums (stats)
__device__ float g_pq[64 * HID];              // per-block partial sum-of-squares
__device__ float g_sum_bc[BATCH * HID];
__device__ float g_ssq_bc[BATCH * HID];

// ---------------- packed fp32x2 helpers (sm_103a FFMA2) ----------------
__device__ __forceinline__ void ffma2(u64& d, u64 a, u64 b) {
    asm("fma.rn.f32x2 %0, %1, %2, %0;" : "+l"(d) : "l"(a), "l"(b));
}
__device__ __forceinline__ u64 pack2(float lo, float hi) {
    u64 r; asm("mov.b64 %0, {%1, %2};" : "=l"(r) : "f"(lo), "f"(hi)); return r;
}
__device__ __forceinline__ void unpack2(float& lo, float& hi, u64 v) {
    asm("mov.b64 {%0, %1}, %2;" : "=f"(lo), "=f"(hi) : "l"(v));
}

__device__ __forceinline__ float gelu_f(float v) {
    // jax.nn.gelu approximate=True (tanh form); fast exp-based tanh (~1e-7 err)
    float a = 0.7978845608028654f * (v + 0.044715f * v * v * v);
    float t = 1.0f - __fdividef(2.0f, __expf(2.0f * a) + 1.0f);
    return 0.5f * v * (1.0f + t);
}

// linspace(-1,1,16) bit-exact: rn(-1 + rn(i * rn(2/15)))
__device__ __forceinline__ float grid_coord(int i) {
    const float delta = 2.0f / 15.0f;
    return __fadd_rn(-1.0f, __fmul_rn((float)i, delta));
}

// ---------------- KNN: warp per (b, g) voxel ----------------
// Distances bit-match the reference:
//   d = (gn + pn) - 2*e,  e = fma(gz,pz, fma(gy,py, mul(gx,px)))
// Register top-8 kept sorted ASCENDING by (d, idx); new candidates always have
// larger index than stored ones, so strict d-compares implement the exact
// lexicographic (d, idx) semantics of jax stable top_k.
__global__ void knn_kernel(const float* __restrict__ pos) {
    __shared__ float4 sp[CHUNK];
    int b = blockIdx.y;
    int t = threadIdx.x;
    int warp = t >> 5, lane = t & 31;
    int g = blockIdx.x * 8 + warp;

    float gx = grid_coord(g >> 8);
    float gy = grid_coord((g >> 4) & 15);
    float gz = grid_coord(g & 15);
    float gn = __fadd_rn(__fadd_rn(__fmul_rn(gx, gx), __fmul_rn(gy, gy)), __fmul_rn(gz, gz));

    float bd[KN]; int bi[KN];
#pragma unroll
    for (int j = 0; j < KN; j++) { bd[j] = 3e38f; bi[j] = 0x7fffffff; }

    for (int base = 0; base < NPTS; base += CHUNK) {
        __syncthreads();
        const float* pb = pos + (b * NPTS + base) * 3;
        for (int i = t; i < CHUNK; i += 256) {
            float x = pb[i * 3 + 0], y = pb[i * 3 + 1], z = pb[i * 3 + 2];
            float pn = __fadd_rn(__fadd_rn(__fmul_rn(x, x), __fmul_rn(y, y)), __fmul_rn(z, z));
            sp[i] = make_float4(x, y, z, pn);
        }
        __syncthreads();

        for (int n = lane; n < CHUNK; n += 128) {   // 4 candidates per iter
            float d[4];
#pragma unroll
            for (int u = 0; u < 4; u++) {
                float4 p = sp[n + 32 * u];
                float e = fmaf(gz, p.z, fmaf(gy, p.y, __fmul_rn(gx, p.x)));
                d[u] = __fsub_rn(__fadd_rn(gn, p.w), __fmul_rn(2.0f, e));
            }
            float m = fminf(fminf(d[0], d[1]), fminf(d[2], d[3]));
            if (m < bd[KN - 1]) {
#pragma unroll
                for (int u = 0; u < 4; u++) {
                    float dv = d[u];
                    if (dv < bd[KN - 1]) {
                        int ii = base + n + 32 * u;
                        bool p[KN];
#pragma unroll
                        for (int j = 0; j < KN; j++) p[j] = (bd[j] > dv);
#pragma unroll
                        for (int j = KN - 1; j >= 1; j--) {
                            bd[j] = p[j - 1] ? bd[j - 1] : (p[j] ? dv : bd[j]);
                            bi[j] = p[j - 1] ? bi[j - 1] : (p[j] ? ii : bi[j]);
                        }
                        if (p[0]) { bd[0] = dv; bi[0] = ii; }
                    }
                }
            }
        }
    }

    // merge: 8 rounds of warp-wide lex-min extraction; winner shifts its array
    for (int sel = 0; sel < KN; sel++) {
        float v = bd[0]; int vi = bi[0]; int vl = lane;
#pragma unroll
        for (int off = 16; off; off >>= 1) {
            float ov = __shfl_xor_sync(0xffffffffu, v, off);
            int   oi = __shfl_xor_sync(0xffffffffu, vi, off);
            int   ol = __shfl_xor_sync(0xffffffffu, vl, off);
            if (ov < v || (ov == v && oi < vi)) { v = ov; vi = oi; vl = ol; }
        }
        if (lane == 0) g_knn[(b * GG + g) * KN + sel] = vi;
        if (lane == vl) {
#pragma unroll
            for (int j = 0; j < KN - 1; j++) { bd[j] = bd[j + 1]; bi[j] = bi[j + 1]; }
            bd[KN - 1] = 3e38f; bi[KN - 1] = 0x7fffffff;
        }
    }
}

// ---------------- Edge (BipartiteConv + update net): warp per voxel ----------------
__global__ void edge_kernel(const float* __restrict__ pos, const float* __restrict__ xin,
                            const float* __restrict__ pe_w1, const float* __restrict__ pe_b1,
                            const float* __restrict__ pe_w2, const float* __restrict__ pe_b2,
                            const float* __restrict__ f_w, const float* __restrict__ f_b,
                            const float* __restrict__ up_w, const float* __restrict__ up_b) {
    __shared__ __align__(16) float s_w2[HID * HID];
    __shared__ __align__(16) float s_up[HID * HID];
    __shared__ float s_pw1[3 * HID], s_pb1[HID], s_pb2[HID], s_fw[3 * HID], s_fb[HID], s_ub[HID];
    __shared__ __align__(16) float s_h1[8][KN][HID];
    __shared__ __align__(16) float s_agg[8][HID];

    int t = threadIdx.x;
    for (int i = t; i < HID * HID; i += 256) { s_w2[i] = pe_w2[i]; s_up[i] = up_w[i]; }
    if (t < 192) { s_pw1[t] = pe_w1[t]; s_fw[t] = f_w[t]; }
    if (t < 64)  { s_pb1[t] = pe_b1[t]; s_pb2[t] = pe_b2[t]; s_fb[t] = f_b[t]; s_ub[t] = up_b[t]; }
    __syncthreads();

    int warp = t >> 5, lane = t & 31;
    int b = blockIdx.y;
    int g = blockIdx.x * 8 + warp;
    float gx = grid_coord(g >> 8);
    float gy = grid_coord((g >> 4) & 15);
    float gz = grid_coord(g & 15);

    int o0 = 2 * lane, o1 = o0 + 1;
    float fm0[KN], fm1[KN];

#pragma unroll
    for (int k = 0; k < KN; k++) {
        int nidx = g_knn[(b * GG + g) * KN + k];
        const float* pp = pos + (b * NPTS + nidx) * 3;
        float rx = pp[0] - gx, ry = pp[1] - gy, rz = pp[2] - gz;
        const float* xp = xin + (b * NPTS + nidx) * 3;
        float f0 = xp[0], f1 = xp[1], f2 = xp[2];

        float h0 = s_pb1[o0] + rx * s_pw1[o0] + ry * s_pw1[64 + o0] + rz * s_pw1[128 + o0];
        float h1 = s_pb1[o1] + rx * s_pw1[o1] + ry * s_pw1[64 + o1] + rz * s_pw1[128 + o1];
        s_h1[warp][k][o0] = gelu_f(h0);
        s_h1[warp][k][o1] = gelu_f(h1);

        fm0[k] = s_fb[o0] + f0 * s_fw[o0] + f1 * s_fw[64 + o0] + f2 * s_fw[128 + o0];
        fm1[k] = s_fb[o1] + f0 * s_fw[o1] + f1 * s_fw[64 + o1] + f2 * s_fw[128 + o1];
    }
    __syncwarp();

    float a0 = 0.0f, a1 = 0.0f;
    for (int k = 0; k < KN; k++) {
        u64 pe01 = pack2(s_pb2[o0], s_pb2[o1]);
#pragma unroll
        for (int c = 0; c < HID; c += 4) {
            float4 av = *(const float4*)&s_h1[warp][k][c];
            u64 w0 = *(const u64*)&s_w2[(c + 0) * HID + o0];
            u64 w1 = *(const u64*)&s_w2[(c + 1) * HID + o0];
            u64 w2 = *(const u64*)&s_w2[(c + 2) * HID + o0];
            u64 w3 = *(const u64*)&s_w2[(c + 3) * HID + o0];
            ffma2(pe01, pack2(av.x, av.x), w0);
            ffma2(pe01, pack2(av.y, av.y), w1);
            ffma2(pe01, pack2(av.z, av.z), w2);
            ffma2(pe01, pack2(av.w, av.w), w3);
        }
        float pe0, pe1; unpack2(pe0, pe1, pe01);
        a0 = fmaf(pe0, fm0[k], a0);
        a1 = fmaf(pe1, fm1[k], a1);
    }
    a0 *= (1.0f / KN);
    a1 *= (1.0f / KN);
    s_agg[warp][o0] = a0;
    s_agg[warp][o1] = a1;
    __syncwarp();

    u64 u01 = pack2(s_ub[o0], s_ub[o1]);
#pragma unroll
    for (int c = 0; c < HID; c += 4) {
        float4 av = *(const float4*)&s_agg[warp][c];
        u64 w0 = *(const u64*)&s_up[(c + 0) * HID + o0];
        u64 w1 = *(const u64*)&s_up[(c + 1) * HID + o0];
        u64 w2 = *(const u64*)&s_up[(c + 2) * HID + o0];
        u64 w3 = *(const u64*)&s_up[(c + 3) * HID + o0];
        ffma2(u01, pack2(av.x, av.x), w0);
        ffma2(u01, pack2(av.y, av.y), w1);
        ffma2(u01, pack2(av.z, av.z), w2);
        ffma2(u01, pack2(av.w, av.w), w3);
    }
    float u0, u1; unpack2(u0, u1, u01);
    u0 = gelu_f(u0);
    u1 = gelu_f(u1);

    // vol[b][c][iz][iy][ix], g = ix*256 + iy*16 + iz
    int iz = g & 15, iy = (g >> 4) & 15, ix = g >> 8;
    int sp = iz * 256 + iy * 16 + ix;
    g_vol[(b * HID + o0) * GG + sp] = u0;
    g_vol[(b * HID + o1) * GG + sp] = u1;
}

// ---------------- direct 3x3x3 conv, SAME, 64->64, FFMA2, fused partial stats ----------------
template <int DIM, int CI, int OG, bool BNRELU>
__global__ void conv_kernel(const float* __restrict__ in, const float* __restrict__ w,
                            const float* __restrict__ bias, float* __restrict__ out) {
    constexpr int P = DIM + 2;
    constexpr int NW = (DIM * DIM) / 32;
    __shared__ float s_in[3 * CI * P * P];
    __shared__ __align__(16) float s_w[27 * CI * OG];
    __shared__ float sred_s[NW][OG], sred_q[NW][OG];

    int z = blockIdx.x, b = blockIdx.y, o0 = blockIdx.z * OG;
    int t = threadIdx.x;
    int y = t / DIM, x = t % DIM;

    u64 accP[OG / 2];
#pragma unroll
    for (int q = 0; q < OG / 2; q++) accP[q] = pack2(bias[o0 + 2 * q], bias[o0 + 2 * q + 1]);

    for (int cc = 0; cc < HID; cc += CI) {
        __syncthreads();
        for (int i = t; i < 3 * CI * P * P; i += DIM * DIM) {
            int xx = i % P; int r = i / P; int yy = r % P; r /= P;
            int ci = r % CI; int pz = r / CI;
            int gz = z + pz - 1, gy = yy - 1, gx = xx - 1;
            float v = 0.0f;
            if (gz >= 0 && gz < DIM && gy >= 0 && gy < DIM && gx >= 0 && gx < DIM) {
                v = in[(((b * HID + cc + ci) * DIM + gz) * DIM + gy) * DIM + gx];
                if (BNRELU) v = fmaxf(0.0f, (v - g_mean[cc + ci]) * g_inv[cc + ci]);
            }
            s_in[i] = v;
        }
        for (int i = t; i < 27 * CI * OG; i += DIM * DIM) {
            int og = i % OG; int r = i / OG; int ci = r % CI; int tap = r / CI;
            s_w[i] = w[((o0 + og) * HID + cc + ci) * 27 + tap];
        }
        __syncthreads();

#pragma unroll 1
        for (int tap = 0; tap < 27; tap++) {
            int kd = tap / 9, kh = (tap / 3) % 3, kw = tap % 3;
            const float* ap = &s_in[(kd * CI) * P * P + (y + kh) * P + (x + kw)];
            const u64* wp2 = (const u64*)&s_w[tap * CI * OG];
#pragma unroll
            for (int ci = 0; ci < CI; ci++) {
                float a = ap[ci * P * P];
                u64 a2 = pack2(a, a);
#pragma unroll
                for (int q = 0; q < OG / 2; q++)
                    ffma2(accP[q], a2, wp2[ci * (OG / 2) + q]);
            }
        }
    }

    float acc[OG];
#pragma unroll
    for (int q = 0; q < OG / 2; q++) unpack2(acc[2 * q], acc[2 * q + 1], accP[q]);

    int spatial = DIM * DIM * DIM;
#pragma unroll
    for (int q = 0; q < OG; q++)
        out[(b * HID + o0 + q) * spatial + (z * DIM + y) * DIM + x] = acc[q];

    // fused per-block BN partial stats (deterministic: per-block slots, no atomics)
    int warp = t >> 5, lane = t & 31;
#pragma unroll
    for (int q = 0; q < OG; q++) {
        float s = acc[q], qq = acc[q] * acc[q];
#pragma unroll
        for (int off = 16; off; off >>= 1) {
            s += __shfl_xor_sync(0xffffffffu, s, off);
            qq += __shfl_xor_sync(0xffffffffu, qq, off);
        }
        if (lane == 0) { sred_s[warp][q] = s; sred_q[warp][q] = qq; }
    }
    __syncthreads();
    if (t < OG) {
        float S = 0.0f, Q = 0.0f;
#pragma unroll
        for (int wv = 0; wv < NW; wv++) { S += sred_s[wv][t]; Q += sred_q[wv][t]; }
        int pblk = blockIdx.x * BATCH + blockIdx.y;
        g_ps[pblk * HID + o0 + t] = S;
        g_pq[pblk * HID + o0 + t] = Q;
    }
}

// ---------------- finalize BN stats from per-block partials ----------------
__global__ void finalize_stats(int npart, float inv_n) {
    int c = threadIdx.x;  // 64
    float S = 0.0f, Q = 0.0f;
    for (int p = 0; p < npart; p++) { S += g_ps[p * HID + c]; Q += g_pq[p * HID + c]; }
    float m = S * inv_n;
    float var = Q * inv_n - m * m;
    g_mean[c] = m;
    g_inv[c] = rsqrtf(var + 1e-5f);
}

// ---------------- block0: residual + relu + 2x2x2 maxpool ----------------
__global__ void resid_pool_kernel(const float* __restrict__ vol, const float* __restrict__ t2) {
    int c = blockIdx.x, b = blockIdx.y, t = threadIdx.x;  // 512 threads
    float m = g_mean[c], iv = g_inv[c];
    int z = t >> 6, y = (t >> 3) & 7, x = t & 7;
    const float* vb = vol + (b * HID + c) * 4096;
    const float* tb = t2 + (b * HID + c) * 4096;
    float best = 0.0f;  // relu outputs are >= 0
#pragma unroll
    for (int dz = 0; dz < 2; dz++)
#pragma unroll
        for (int dy = 0; dy < 2; dy++)
#pragma unroll
            for (int dx = 0; dx < 2; dx++) {
                int idx = ((2 * z + dz) * 16 + 2 * y + dy) * 16 + 2 * x + dx;
                float v = fmaxf(0.0f, vb[idx] + (tb[idx] - m) * iv);
                best = fmaxf(best, v);
            }
    g_vol2[(b * HID + c) * 512 + t] = best;
}

// ---------------- block1: residual + relu, reduce to per-(b,c) sums ----------------
__global__ void resid_sum_kernel(const float* __restrict__ vol2, const float* __restrict__ t2) {
    int c = blockIdx.x, b = blockIdx.y, t = threadIdx.x;  // 512 threads
    float m = g_mean[c], iv = g_inv[c];
    float v = fmaxf(0.0f, vol2[(b * HID + c) * 512 + t] + (t2[(b * HID + c) * 512 + t] - m) * iv);
    float s = v, q = v * v;
#pragma unroll
    for (int off = 16; off; off >>= 1) {
        s += __shfl_xor_sync(0xffffffffu, s, off);
        q += __shfl_xor_sync(0xffffffffu, q, off);
    }
    __shared__ float ss[16], sq[16];
    int warp = t >> 5, lane = t & 31;
    if (lane == 0) { ss[warp] = s; sq[warp] = q; }
    __syncthreads();
    if (t == 0) {
        float S = 0.0f, Q = 0.0f;
        for (int j = 0; j < 16; j++) { S += ss[j]; Q += sq[j]; }
        g_sum_bc[b * HID + c] = S;
        g_ssq_bc[b * HID + c] = Q;
    }
}

// ---------------- final BN + affine + spatial mean + linear head ----------------
__global__ void head_kernel(const float* __restrict__ on_g, const float* __restrict__ on_b,
                            const float* __restrict__ ro_w, const float* __restrict__ ro_b,
                            float* __restrict__ out) {
    __shared__ float pooled[BATCH][HID];
    int t = threadIdx.x;  // 64 threads
    if (t < HID) {
        float S = 0.0f, Q = 0.0f;
        for (int b = 0; b < BATCH; b++) { S += g_sum_bc[b * HID + t]; Q += g_ssq_bc[b * HID + t]; }
        float n = (float)(BATCH * 512);
        float m = S / n;
        float var = Q / n - m * m;
        float iv = rsqrtf(var + 1e-5f);
        for (int b = 0; b < BATCH; b++)
            pooled[b][t] = (g_sum_bc[b * HID + t] * (1.0f / 512.0f) - m) * iv * on_g[t] + on_b[t];
    }
    __syncthreads();
    if (t < 64) {
        int b = t >> 4, j = t & 15;
        float s = ro_b[j];
        for (int c = 0; c < HID; c++) s = fmaf(pooled[b][c], ro_w[c * 16 + j], s);
        out[b * 16 + j] = s;
    }
}

// ---------------- launch ----------------
extern "C" void kernel_launch(void* const* d_in, const int* in_sizes, int n_in,
                              void* d_out, int out_size) {
    const float* pos   = (const float*)d_in[0];
    const float* xin   = (const float*)d_in[1];
    const float* pe_w1 = (const float*)d_in[2];
    const float* pe_b1 = (const float*)d_in[3];
    const float* pe_w2 = (const float*)d_in[4];
    const float* pe_b2 = (const float*)d_in[5];
    const float* f_w   = (const float*)d_in[6];
    const float* f_b   = (const float*)d_in[7];
    const float* up_w  = (const float*)d_in[8];
    const float* up_b  = (const float*)d_in[9];
    const float* conv_w = (const float*)d_in[10];  // [2,2,64,64,3,3,3]
    const float* conv_b = (const float*)d_in[11];  // [2,2,64]
    const float* on_g  = (const float*)d_in[12];
    const float* on_b  = (const float*)d_in[13];
    const float* ro_w  = (const float*)d_in[14];
    const float* ro_b  = (const float*)d_in[15];
    float* out = (float*)d_out;

    float *t1, *t2, *vol, *vol2;
    cudaGetSymbolAddress((void**)&t1, g_t1);
    cudaGetSymbolAddress((void**)&t2, g_t2);
    cudaGetSymbolAddress((void**)&vol, g_vol);
    cudaGetSymbolAddress((void**)&vol2, g_vol2);

    const int WSTRIDE = HID * HID * 27;

    knn_kernel<<<dim3(512, BATCH), 256>>>(pos);
    edge_kernel<<<dim3(512, BATCH), 256>>>(pos, xin, pe_w1, pe_b1, pe_w2, pe_b2,
                                           f_w, f_b, up_w, up_b);

    // block 0 @ 16^3
    conv_kernel<16, 4, 32, false><<<dim3(16, BATCH, 2), 256>>>(vol, conv_w + 0 * WSTRIDE,
                                                               conv_b + 0 * HID, t1);
    finalize_stats<<<1, 64>>>(64, 1.0f / (BATCH * 4096));
    conv_kernel<16, 4, 32, true><<<dim3(16, BATCH, 2), 256>>>(t1, conv_w + 1 * WSTRIDE,
                                                              conv_b + 1 * HID, t2);
    finalize_stats<<<1, 64>>>(64, 1.0f / (BATCH * 4096));
    resid_pool_kernel<<<dim3(64, BATCH), 512>>>(vol, t2);

    // block 1 @ 8^3
    conv_kernel<8, 16, 8, false><<<dim3(8, BATCH, 8), 64>>>(vol2, conv_w + 2 * WSTRIDE,
                                                            conv_b + 2 * HID, t1);
    finalize_stats<<<1, 64>>>(32, 1.0f / (BATCH * 512));
    conv_kernel<8, 16, 8, true><<<dim3(8, BATCH, 8), 64>>>(t1, conv_w + 3 * WSTRIDE,
                                                           conv_b + 3 * HID, t2);
    finalize_stats<<<1, 64>>>(32, 1.0f / (BATCH * 512));
    resid_sum_kernel<<<dim3(64, BATCH), 512>>>(vol2, t2);

    head_kernel<<<1, 64>>>(on_g, on_b, ro_w, ro_b, out);
}